// round 10
// baseline (speedup 1.0000x reference)
#include <cuda_runtime.h>

// Fixed shapes per reference: B=4096, IN=HID=8192, fp32
#define IN_DIM   8192
#define HID_DIM  8192
#define COL4     (IN_DIM / 4)                    // 2048 float4 per row
#define ROW_GRPS 128                             // colsum row groups
#define ROWS_PER_GRP (HID_DIM / ROW_GRPS)        // 64 rows per block

// Device-global scratch (allocation-free rule: device globals allowed)
__device__ float g_partial[ROW_GRPS * IN_DIM];   // 4 MB
__device__ float g_wsum[IN_DIM];                 // 32 KB

// ---------------- Kernel 1: partial column sums of W [HID, IN] ----------------
// grid = (8, 128) = 1024 blocks, block = 256. 81.3% of spec (R9) — keep.
__global__ __launch_bounds__(256) void colsum_partial(const float* __restrict__ w) {
    const int col4 = blockIdx.x * 256 + threadIdx.x;        // 0..2047
    const int r0   = blockIdx.y * ROWS_PER_GRP;
    const float4* __restrict__ w4 = reinterpret_cast<const float4*>(w);

    float4 acc = make_float4(0.f, 0.f, 0.f, 0.f);
    #pragma unroll 8
    for (int r = 0; r < ROWS_PER_GRP; ++r) {
        float4 v = __ldg(&w4[(size_t)(r0 + r) * COL4 + col4]);
        acc.x += v.x; acc.y += v.y; acc.z += v.z; acc.w += v.w;
    }
    reinterpret_cast<float4*>(g_partial)[(size_t)blockIdx.y * COL4 + col4] = acc;
}

// ---------------- Kernel 2: reduce 128 partials -> g_wsum ----------------
// grid = 8, block = 256. ~4 MB of L2-resident traffic, ~2 us.
__global__ __launch_bounds__(256) void reduce_partial() {
    const int col4 = blockIdx.x * 256 + threadIdx.x;
    const float4* __restrict__ p4 = reinterpret_cast<const float4*>(g_partial);
    float4 acc = make_float4(0.f, 0.f, 0.f, 0.f);
    #pragma unroll 8
    for (int g = 0; g < ROW_GRPS; ++g) {
        float4 v = p4[(size_t)g * COL4 + col4];
        acc.x += v.x; acc.y += v.y; acc.z += v.z; acc.w += v.w;
    }
    reinterpret_cast<float4*>(g_wsum)[col4] = acc;
}

// ---------------- Kernel 3: out[b] = 0.75 * dot(x[b], wsum) ----------------
// One row per block (proven shape), block = 128 threads, 16 LDG.128 per
// thread (MLP 16), 4-warp reduce, single barrier, block exits.
__global__ __launch_bounds__(128) void rowdot(const float* __restrict__ x,
                                              float* __restrict__ out) {
    const int t    = threadIdx.x;
    const int lane = t & 31;
    const int wid  = t >> 5;
    const int row  = blockIdx.x;

    const float4* __restrict__ x4 =
        reinterpret_cast<const float4*>(x + (size_t)row * IN_DIM);
    const float4* __restrict__ w4 = reinterpret_cast<const float4*>(g_wsum);

    float acc = 0.f;
    // 2048 float4 / 128 threads = 16 per thread, fully unrolled
    #pragma unroll
    for (int k = 0; k < COL4 / 128; ++k) {
        const int i = t + k * 128;
        float4 xv = __ldg(&x4[i]);
        float4 wv = __ldg(&w4[i]);             // L1-resident after warmup
        acc = fmaf(xv.x, wv.x, acc);
        acc = fmaf(xv.y, wv.y, acc);
        acc = fmaf(xv.z, wv.z, acc);
        acc = fmaf(xv.w, wv.w, acc);
    }

    #pragma unroll
    for (int off = 16; off > 0; off >>= 1)
        acc += __shfl_xor_sync(0xFFFFFFFFu, acc, off);

    __shared__ float warp_sums[4];
    if (lane == 0) warp_sums[wid] = acc;
    __syncthreads();

    if (t == 0) {
        float v = warp_sums[0] + warp_sums[1] + warp_sums[2] + warp_sums[3];
        out[row] = v * 0.75f;                  // (/2) * 1.5
    }
}

extern "C" void kernel_launch(void* const* d_in, const int* in_sizes, int n_in,
                              void* d_out, int out_size) {
    const float* x = (const float*)d_in[0];   // [B, IN]
    const float* w = (const float*)d_in[1];   // [HID, IN]
    float* out = (float*)d_out;               // [B, 1]
    const int B = in_sizes[0] / IN_DIM;

    dim3 g1(COL4 / 256, ROW_GRPS);            // (8, 128)
    colsum_partial<<<g1, 256>>>(w);
    reduce_partial<<<COL4 / 256, 256>>>();
    rowdot<<<B, 128>>>(x, out);
}

// round 11
// speedup vs baseline: 1.1059x; 1.1059x over previous
#include <cuda_runtime.h>

// Fixed shapes per reference: B=4096, IN=HID=8192, fp32
#define IN_DIM   8192
#define HID_DIM  8192
#define COL4     (IN_DIM / 4)                    // 2048 float4 per row
#define ROW_GRPS 128                             // colsum row groups
#define ROWS_PER_GRP (HID_DIM / ROW_GRPS)        // 64 rows per block

// Device-global scratch (allocation-free rule: device globals allowed)
__device__ float g_partial[ROW_GRPS * IN_DIM];   // 4 MB
__device__ float g_wsum[IN_DIM];                 // 32 KB

// ---------------- Kernel 1: partial column sums of W [HID, IN] ----------------
// grid = (8, 128) = 1024 blocks, block = 256. 81.4% of spec (R9/R10) — keep.
__global__ __launch_bounds__(256) void colsum_partial(const float* __restrict__ w) {
    const int col4 = blockIdx.x * 256 + threadIdx.x;        // 0..2047
    const int r0   = blockIdx.y * ROWS_PER_GRP;
    const float4* __restrict__ w4 = reinterpret_cast<const float4*>(w);

    float4 acc = make_float4(0.f, 0.f, 0.f, 0.f);
    #pragma unroll 8
    for (int r = 0; r < ROWS_PER_GRP; ++r) {
        float4 v = __ldg(&w4[(size_t)(r0 + r) * COL4 + col4]);
        acc.x += v.x; acc.y += v.y; acc.z += v.z; acc.w += v.w;
    }
    reinterpret_cast<float4*>(g_partial)[(size_t)blockIdx.y * COL4 + col4] = acc;
}

// ---------------- Kernel 2: reduce 128 partials -> g_wsum (wide) ----------------
// grid = 32, block = 256. Block owns 64 f4-columns; threads split the 128
// groups 4 ways (32 each), smem-combine in fixed order -> deterministic.
__global__ __launch_bounds__(256) void reduce_partial() {
    const int t    = threadIdx.x;
    const int cl   = t & 63;                    // column within block
    const int gq   = t >> 6;                    // group quarter 0..3
    const int col4 = blockIdx.x * 64 + cl;
    const float4* __restrict__ p4 = reinterpret_cast<const float4*>(g_partial);

    float4 acc = make_float4(0.f, 0.f, 0.f, 0.f);
    #pragma unroll 8
    for (int i = 0; i < 32; ++i) {              // 32 groups per quarter
        float4 v = p4[(size_t)(gq * 32 + i) * COL4 + col4];
        acc.x += v.x; acc.y += v.y; acc.z += v.z; acc.w += v.w;
    }

    __shared__ float4 s[4][64];
    s[gq][cl] = acc;
    __syncthreads();

    if (t < 64) {
        float4 a = s[0][t], b = s[1][t], c = s[2][t], d = s[3][t];
        float4 r;
        r.x = (a.x + b.x) + (c.x + d.x);
        r.y = (a.y + b.y) + (c.y + d.y);
        r.z = (a.z + b.z) + (c.z + d.z);
        r.w = (a.w + b.w) + (c.w + d.w);
        reinterpret_cast<float4*>(g_wsum)[blockIdx.x * 64 + t] = r;
    }
}

// ---------------- Kernel 3: out[b] = 0.75 * dot(x[b], wsum) ----------------
// R1's proven shape, byte-for-byte: one row per block, 256 threads,
// 8 LDG.128 on x (MLP=8), single barrier, block exits.
__global__ __launch_bounds__(256) void rowdot(const float* __restrict__ x,
                                              float* __restrict__ out) {
    const int b = blockIdx.x;
    const float4* __restrict__ x4 =
        reinterpret_cast<const float4*>(x + (size_t)b * IN_DIM);
    const float4* __restrict__ w4 = reinterpret_cast<const float4*>(g_wsum);

    float acc = 0.f;
    #pragma unroll
    for (int k = 0; k < COL4 / 256; ++k) {
        const int i = threadIdx.x + k * 256;
        float4 xv = __ldg(&x4[i]);
        float4 wv = w4[i];
        acc = fmaf(xv.x, wv.x, acc);
        acc = fmaf(xv.y, wv.y, acc);
        acc = fmaf(xv.z, wv.z, acc);
        acc = fmaf(xv.w, wv.w, acc);
    }

    #pragma unroll
    for (int off = 16; off > 0; off >>= 1)
        acc += __shfl_xor_sync(0xFFFFFFFFu, acc, off);

    __shared__ float warp_sums[8];
    const int lane = threadIdx.x & 31;
    const int wid  = threadIdx.x >> 5;
    if (lane == 0) warp_sums[wid] = acc;
    __syncthreads();

    if (wid == 0) {
        float v = (lane < 8) ? warp_sums[lane] : 0.f;
        #pragma unroll
        for (int off = 4; off > 0; off >>= 1)
            v += __shfl_xor_sync(0xFFFFFFFFu, v, off);
        if (lane == 0) out[b] = v * 0.75f;   // (/2) * 1.5
    }
}

extern "C" void kernel_launch(void* const* d_in, const int* in_sizes, int n_in,
                              void* d_out, int out_size) {
    const float* x = (const float*)d_in[0];   // [B, IN]
    const float* w = (const float*)d_in[1];   // [HID, IN]
    float* out = (float*)d_out;               // [B, 1]
    const int B = in_sizes[0] / IN_DIM;

    dim3 g1(COL4 / 256, ROW_GRPS);            // (8, 128)
    colsum_partial<<<g1, 256>>>(w);
    reduce_partial<<<32, 256>>>();
    rowdot<<<B, 256>>>(x, out);
}

// round 12
// speedup vs baseline: 1.1205x; 1.0132x over previous
#include <cuda_runtime.h>
#include <cstdint>

// Fixed shapes per reference: B=4096, IN=HID=8192, fp32
#define IN_DIM   8192
#define HID_DIM  8192
#define COL4     (IN_DIM / 4)                    // 2048 float4 per row
#define ROW_BYTES (IN_DIM * 4)                   // 32 KB per x row
#define ROW_GRPS 128                             // colsum row groups
#define ROWS_PER_GRP (HID_DIM / ROW_GRPS)        // 64 rows per block

// Device-global scratch (allocation-free rule: device globals allowed)
__device__ float g_partial[ROW_GRPS * IN_DIM];   // 4 MB
__device__ float g_wsum[IN_DIM];                 // 32 KB

// ---------------- Kernel 1: partial column sums of W [HID, IN] ----------------
// grid = (8, 128), block = 256. 81.6% of spec (R11) — frozen.
__global__ __launch_bounds__(256) void colsum_partial(const float* __restrict__ w) {
    const int col4 = blockIdx.x * 256 + threadIdx.x;        // 0..2047
    const int r0   = blockIdx.y * ROWS_PER_GRP;
    const float4* __restrict__ w4 = reinterpret_cast<const float4*>(w);

    float4 acc = make_float4(0.f, 0.f, 0.f, 0.f);
    #pragma unroll 8
    for (int r = 0; r < ROWS_PER_GRP; ++r) {
        float4 v = __ldg(&w4[(size_t)(r0 + r) * COL4 + col4]);
        acc.x += v.x; acc.y += v.y; acc.z += v.z; acc.w += v.w;
    }
    reinterpret_cast<float4*>(g_partial)[(size_t)blockIdx.y * COL4 + col4] = acc;
}

// ---------------- Kernel 2: wide reduce 128 partials -> g_wsum ----------------
// grid = 32, block = 256 (R11 version, ~1 us) — frozen.
__global__ __launch_bounds__(256) void reduce_partial() {
    const int t    = threadIdx.x;
    const int cl   = t & 63;
    const int gq   = t >> 6;
    const int col4 = blockIdx.x * 64 + cl;
    const float4* __restrict__ p4 = reinterpret_cast<const float4*>(g_partial);

    float4 acc = make_float4(0.f, 0.f, 0.f, 0.f);
    #pragma unroll 8
    for (int i = 0; i < 32; ++i) {
        float4 v = p4[(size_t)(gq * 32 + i) * COL4 + col4];
        acc.x += v.x; acc.y += v.y; acc.z += v.z; acc.w += v.w;
    }

    __shared__ float4 s[4][64];
    s[gq][cl] = acc;
    __syncthreads();

    if (t < 64) {
        float4 a = s[0][t], b = s[1][t], c = s[2][t], d = s[3][t];
        float4 r;
        r.x = (a.x + b.x) + (c.x + d.x);
        r.y = (a.y + b.y) + (c.y + d.y);
        r.z = (a.z + b.z) + (c.z + d.z);
        r.w = (a.w + b.w) + (c.w + d.w);
        reinterpret_cast<float4*>(g_wsum)[blockIdx.x * 64 + t] = r;
    }
}

// ---------------- Kernel 3: TMA-staged rowdot ----------------
// One row per block. Thread 0 issues a single 32 KB cp.async.bulk of x[row]
// into smem (no L1tex wavefronts), block waits on the mbarrier, then dots
// against L1-resident wsum. CTA overlap (7/SM) hides the TMA latency.
__global__ __launch_bounds__(256) void rowdot_tma(const float* __restrict__ x,
                                                  float* __restrict__ out) {
    __shared__ alignas(128) float4 sx[COL4];            // 32 KB
    __shared__ alignas(8)  unsigned long long mbar;

    const int t    = threadIdx.x;
    const int lane = t & 31;
    const int wid  = t >> 5;
    const int b    = blockIdx.x;

    const uint32_t smbar = (uint32_t)__cvta_generic_to_shared(&mbar);
    const uint32_t sdst  = (uint32_t)__cvta_generic_to_shared(sx);

    if (t == 0) {
        asm volatile("mbarrier.init.shared.b64 [%0], 1;" :: "r"(smbar) : "memory");
        asm volatile("fence.proxy.async.shared::cta;" ::: "memory");
        asm volatile("mbarrier.arrive.expect_tx.shared.b64 _, [%0], %1;"
                     :: "r"(smbar), "r"(ROW_BYTES) : "memory");
        asm volatile("cp.async.bulk.shared::cta.global.mbarrier::complete_tx::bytes "
                     "[%0], [%1], %2, [%3];"
                     :: "r"(sdst), "l"(x + (size_t)b * IN_DIM),
                        "r"(ROW_BYTES), "r"(smbar) : "memory");
    }
    __syncthreads();   // orders mbarrier.init before other threads wait

    // Wait phase 0 (fresh barrier each launch)
    {
        uint32_t done;
        asm volatile(
            "{\n\t.reg .pred p;\n\t"
            "WAIT_%=:\n\t"
            "mbarrier.try_wait.parity.shared.b64 p, [%1], 0, 0x989680;\n\t"
            "selp.b32 %0, 1, 0, p;\n\t"
            "@!p bra WAIT_%=;\n\t}"
            : "=r"(done) : "r"(smbar) : "memory");
    }

    const float4* __restrict__ w4 = reinterpret_cast<const float4*>(g_wsum);

    float acc = 0.f;
    #pragma unroll
    for (int k = 0; k < COL4 / 256; ++k) {              // 8 steps from smem
        const int i = t + k * 256;
        float4 xv = sx[i];
        float4 wv = __ldg(&w4[i]);                      // L1-resident
        acc = fmaf(xv.x, wv.x, acc);
        acc = fmaf(xv.y, wv.y, acc);
        acc = fmaf(xv.z, wv.z, acc);
        acc = fmaf(xv.w, wv.w, acc);
    }

    #pragma unroll
    for (int off = 16; off > 0; off >>= 1)
        acc += __shfl_xor_sync(0xFFFFFFFFu, acc, off);

    __shared__ float warp_sums[8];
    if (lane == 0) warp_sums[wid] = acc;
    __syncthreads();

    if (wid == 0) {
        float v = (lane < 8) ? warp_sums[lane] : 0.f;
        #pragma unroll
        for (int off = 4; off > 0; off >>= 1)
            v += __shfl_xor_sync(0xFFFFFFFFu, v, off);
        if (lane == 0) out[b] = v * 0.75f;              // (/2) * 1.5
    }
}

extern "C" void kernel_launch(void* const* d_in, const int* in_sizes, int n_in,
                              void* d_out, int out_size) {
    const float* x = (const float*)d_in[0];   // [B, IN]
    const float* w = (const float*)d_in[1];   // [HID, IN]
    float* out = (float*)d_out;               // [B, 1]
    const int B = in_sizes[0] / IN_DIM;

    dim3 g1(COL4 / 256, ROW_GRPS);            // (8, 128)
    colsum_partial<<<g1, 256>>>(w);
    reduce_partial<<<32, 256>>>();
    rowdot_tma<<<B, 256>>>(x, out);
}